// round 3
// baseline (speedup 1.0000x reference)
#include <cuda_runtime.h>
#include <math.h>

#define BSZ 32
#define SEQL 2048
#define INF 512
#define HID 256
#define MTOT (BSZ * SEQL)           // 65536 rows
#define XXN (BSZ * SEQL * 2 * HID)  // 33554432
#define HOUTN (4 * BSZ * HID)       // 32768

// ---------------- scratch (static device globals; no allocation) -------------
__device__ float g_H [MTOT * HID];
__device__ float g_G1[MTOT * HID];
__device__ float g_Yl[MTOT * HID];
__device__ float g_Yr[MTOT * HID];
__device__ float g_Ga[MTOT * HID];
__device__ float g_Gb[MTOT * HID];
__device__ float g_hdump[4 * BSZ * HID];

// ---------------- fp32 SGEMM: C[M,N] = act(A[M,K] @ W[N,K]^T + bias[N]) ------
// Tile 128(M) x 64(N) x 16(K), 256 threads, 8x4 microtile, double-buffered smem.
// Requires: M % 128 == 0, N % 64 == 0, K % 16 == 0 (true for all our shapes).
template <int ACT>
__global__ __launch_bounds__(256, 2)
void gemm_bias_kernel(const float* __restrict__ A, const float* __restrict__ W,
                      const float* __restrict__ bias, float* __restrict__ C,
                      int M, int K, int N)
{
    __shared__ float As[2][16][132];
    __shared__ float Bs[2][16][68];

    const int tid = threadIdx.x;
    const int bm = blockIdx.x * 128;
    const int bn = blockIdx.y * 64;

    // global-load mapping
    const int am = tid >> 2;            // 0..63 (second f4 -> +64)
    const int ak = (tid & 3) * 4;       // 0,4,8,12
    const int wn = tid >> 2;            // 0..63
    const int wk = (tid & 3) * 4;

    const float* Ap0 = A + (size_t)(bm + am) * K + ak;
    const float* Ap1 = A + (size_t)(bm + am + 64) * K + ak;
    const float* Wp  = W + (size_t)(bn + wn) * K + wk;

    // compute mapping
    const int tm = (tid & 15) * 8;      // 0..120
    const int tn = (tid >> 4) * 4;      // 0..60

    float acc[8][4];
#pragma unroll
    for (int i = 0; i < 8; i++)
#pragma unroll
        for (int j = 0; j < 4; j++) acc[i][j] = 0.0f;

    // prologue: tile 0 -> smem buf 0
    float4 a0 = *reinterpret_cast<const float4*>(Ap0);
    float4 a1 = *reinterpret_cast<const float4*>(Ap1);
    float4 b0 = *reinterpret_cast<const float4*>(Wp);
    As[0][ak + 0][am]      = a0.x; As[0][ak + 1][am]      = a0.y;
    As[0][ak + 2][am]      = a0.z; As[0][ak + 3][am]      = a0.w;
    As[0][ak + 0][am + 64] = a1.x; As[0][ak + 1][am + 64] = a1.y;
    As[0][ak + 2][am + 64] = a1.z; As[0][ak + 3][am + 64] = a1.w;
    Bs[0][wk + 0][wn] = b0.x; Bs[0][wk + 1][wn] = b0.y;
    Bs[0][wk + 2][wn] = b0.z; Bs[0][wk + 3][wn] = b0.w;
    __syncthreads();

    const int nk = K >> 4;
    for (int kt = 0; kt < nk; kt++) {
        const int buf = kt & 1;
        const bool more = (kt + 1) < nk;
        if (more) {
            a0 = *reinterpret_cast<const float4*>(Ap0 + (kt + 1) * 16);
            a1 = *reinterpret_cast<const float4*>(Ap1 + (kt + 1) * 16);
            b0 = *reinterpret_cast<const float4*>(Wp  + (kt + 1) * 16);
        }
#pragma unroll
        for (int k = 0; k < 16; k++) {
            float4 x0 = *reinterpret_cast<const float4*>(&As[buf][k][tm]);
            float4 x1 = *reinterpret_cast<const float4*>(&As[buf][k][tm + 4]);
            float4 y0 = *reinterpret_cast<const float4*>(&Bs[buf][k][tn]);
            float av[8] = {x0.x, x0.y, x0.z, x0.w, x1.x, x1.y, x1.z, x1.w};
            float bv[4] = {y0.x, y0.y, y0.z, y0.w};
#pragma unroll
            for (int i = 0; i < 8; i++)
#pragma unroll
                for (int j = 0; j < 4; j++)
                    acc[i][j] = fmaf(av[i], bv[j], acc[i][j]);
        }
        if (more) {
            const int nb = buf ^ 1;
            As[nb][ak + 0][am]      = a0.x; As[nb][ak + 1][am]      = a0.y;
            As[nb][ak + 2][am]      = a0.z; As[nb][ak + 3][am]      = a0.w;
            As[nb][ak + 0][am + 64] = a1.x; As[nb][ak + 1][am + 64] = a1.y;
            As[nb][ak + 2][am + 64] = a1.z; As[nb][ak + 3][am + 64] = a1.w;
            Bs[nb][wk + 0][wn] = b0.x; Bs[nb][wk + 1][wn] = b0.y;
            Bs[nb][wk + 2][wn] = b0.z; Bs[nb][wk + 3][wn] = b0.w;
            __syncthreads();
        }
    }

    // epilogue
    float4 bb = *reinterpret_cast<const float4*>(&bias[bn + tn]);
#pragma unroll
    for (int i = 0; i < 8; i++) {
        float4 r;
        r.x = acc[i][0] + bb.x;
        r.y = acc[i][1] + bb.y;
        r.z = acc[i][2] + bb.z;
        r.w = acc[i][3] + bb.w;
        if (ACT == 1) {  // sigmoid
            r.x = 1.0f / (1.0f + expf(-r.x));
            r.y = 1.0f / (1.0f + expf(-r.y));
            r.z = 1.0f / (1.0f + expf(-r.z));
            r.w = 1.0f / (1.0f + expf(-r.w));
        }
        *reinterpret_cast<float4*>(&C[(size_t)(bm + tm + i) * N + bn + tn]) = r;
    }
}

// ---------------- sequential scan (both directions in one launch) ------------
// h_{t+1} = tanh(x_t * (g_t*h + (1-g_t)*x_t)); g precomputed by the gate GEMM.
// First 8192 threads: forward over (xF,gF)->yF; next 8192: reverse over
// (xR,gR)->yR (reads/writes at original time index, iterating t = SEQ-1 .. 0).
__global__ __launch_bounds__(64)
void scan_kernel(const float* __restrict__ xF, const float* __restrict__ gF,
                 float* __restrict__ yF, float* __restrict__ hF,
                 const float* __restrict__ xR, const float* __restrict__ gR,
                 float* __restrict__ yR, float* __restrict__ hR,
                 int ystride, int yoffF, int yoffR)
{
    const int gid = blockIdx.x * 64 + threadIdx.x;   // 0..16383
    const int dir = gid >> 13;
    const int id  = gid & 8191;
    const int b = id >> 8;
    const int j = id & 255;

    const float *xp, *gp;
    float *yp, *hp;
    int t0, dt, yo;
    if (dir == 0) { xp = xF; gp = gF; yp = yF; hp = hF; t0 = 0;        dt =  1; yo = yoffF; }
    else          { xp = xR; gp = gR; yp = yR; hp = hR; t0 = SEQL - 1; dt = -1; yo = yoffR; }

    const int base  = b * SEQL * HID + j;
    const int ybase = b * SEQL * ystride + yo + j;

    float h = 0.0f;
#pragma unroll 4
    for (int s = 0; s < SEQL; s++) {
        const int t = t0 + dt * s;
        const float xv = __ldg(xp + base + t * HID);
        const float g  = __ldg(gp + base + t * HID);
        const float r  = fmaf(g, h, (1.0f - g) * xv);
        h = tanhf(xv * r);
        yp[ybase + t * ystride] = h;
    }
    hp[(b << 8) + j] = h;
}

// ---------------- launch ----------------
extern "C" void kernel_launch(void* const* d_in, const int* in_sizes, int n_in,
                              void* d_out, int out_size)
{
    const float* x    = (const float*)d_in[0];  // [32,2048,512]
    const float* W_fc = (const float*)d_in[1];  // [256,512]
    const float* b_fc = (const float*)d_in[2];  // [256]
    // d_in[3] (W1), d_in[4] (b1): mathematically dead (blending1 == identity)
    const float* W2   = (const float*)d_in[5];  // [2,256,256]
    const float* b2   = (const float*)d_in[6];  // [2,256]
    float* out = (float*)d_out;

    float *H, *G1, *Yl, *Yr, *Ga, *Gb, *hd;
    cudaGetSymbolAddress((void**)&H,  g_H);
    cudaGetSymbolAddress((void**)&G1, g_G1);
    cudaGetSymbolAddress((void**)&Yl, g_Yl);
    cudaGetSymbolAddress((void**)&Yr, g_Yr);
    cudaGetSymbolAddress((void**)&Ga, g_Ga);
    cudaGetSymbolAddress((void**)&Gb, g_Gb);
    cudaGetSymbolAddress((void**)&hd, g_hdump);

    // h_out region (guard in case out_size only covers xx)
    float* hout = (out_size >= XXN + HOUTN) ? (out + XXN) : hd;

    const dim3 blk(256);
    const dim3 grd(MTOT / 128, HID / 64);

    // 1) input projection: H = x @ W_fc^T + b_fc          [65536 x 256]
    gemm_bias_kernel<0><<<grd, blk>>>(x, W_fc, b_fc, H, MTOT, INF, HID);
    // 2) layer-1 gates (shared by both directions): G1 = sigmoid(H @ W2[0]^T + b2[0])
    gemm_bias_kernel<1><<<grd, blk>>>(H, W2, b2, G1, MTOT, HID, HID);
    // 3) layer-1 scans: fwd -> Yl (+h_out[0]), rev -> Yr (+h_out[1])
    scan_kernel<<<256, 64>>>(H, G1, Yl, hout,
                             H, G1, Yr, hout + BSZ * HID,
                             HID, 0, 0);
    // 4) layer-2 gates (per direction, W2[1])
    gemm_bias_kernel<1><<<grd, blk>>>(Yl, W2 + HID * HID, b2 + HID, Ga, MTOT, HID, HID);
    gemm_bias_kernel<1><<<grd, blk>>>(Yr, W2 + HID * HID, b2 + HID, Gb, MTOT, HID, HID);
    // 5) layer-2 scans write straight into d_out xx[:, :, 0:256] / [:, :, 256:512]
    scan_kernel<<<256, 64>>>(Yl, Ga, out, hout + 2 * BSZ * HID,
                             Yr, Gb, out, hout + 3 * BSZ * HID,
                             2 * HID, 0, HID);
}

// round 6
// speedup vs baseline: 3.2045x; 3.2045x over previous
#include <cuda_runtime.h>
#include <cuda_bf16.h>
#include <math.h>
#include <stdint.h>

#define BSZ 32
#define SEQL 2048
#define INF 512
#define HID 256
#define MTOT (BSZ * SEQL)           // 65536 rows
#define XXN (BSZ * SEQL * 2 * HID)  // 33554432
#define HOUTN (4 * BSZ * HID)       // 32768

// ---------------- scratch (static device globals; no allocation) -------------
__device__ __nv_bfloat16 g_xhi [MTOT * INF];
__device__ __nv_bfloat16 g_xlo [MTOT * INF];
__device__ __nv_bfloat16 g_Wfc3[HID * 3 * INF];       // [Whi|Whi|Wlo] along k'
__device__ __nv_bfloat16 g_W23 [2 * HID * 3 * HID];
__device__ __nv_bfloat16 g_Hhi [MTOT * HID];
__device__ __nv_bfloat16 g_Hlo [MTOT * HID];
__device__ float         g_G1  [MTOT * HID];
__device__ __nv_bfloat16 g_Ylhi[MTOT * HID];
__device__ __nv_bfloat16 g_Yllo[MTOT * HID];
__device__ __nv_bfloat16 g_Yrhi[MTOT * HID];
__device__ __nv_bfloat16 g_Yrlo[MTOT * HID];
__device__ float         g_Ga  [MTOT * HID];
__device__ float         g_Gb  [MTOT * HID];
__device__ float         g_hdump[4 * BSZ * HID];

// ---------------- fast math ----------------
__device__ __forceinline__ float fast_ex2(float x) {
    float y; asm("ex2.approx.f32 %0, %1;" : "=f"(y) : "f"(x)); return y;
}
__device__ __forceinline__ float fast_rcp(float x) {
    float y; asm("rcp.approx.f32 %0, %1;" : "=f"(y) : "f"(x)); return y;
}
__device__ __forceinline__ float fast_sigmoid(float z) {
    return fast_rcp(1.0f + fast_ex2(-1.4426950408889634f * z));
}
__device__ __forceinline__ void split_bf16(float v, __nv_bfloat16& hi, __nv_bfloat16& lo) {
    hi = __float2bfloat16(v);
    lo = __float2bfloat16(v - __bfloat162float(hi));
}

// ---------------- PTX helpers ----------------
__device__ __forceinline__ void ldsm4(uint32_t (&r)[4], uint32_t saddr) {
    asm volatile("ldmatrix.sync.aligned.m8n8.x4.shared.b16 {%0,%1,%2,%3}, [%4];"
                 : "=r"(r[0]), "=r"(r[1]), "=r"(r[2]), "=r"(r[3]) : "r"(saddr));
}
__device__ __forceinline__ void mma16816(float (&d)[4], const uint32_t (&a)[4],
                                         uint32_t b0, uint32_t b1) {
    asm volatile("mma.sync.aligned.m16n8k16.row.col.f32.bf16.bf16.f32 "
                 "{%0,%1,%2,%3}, {%4,%5,%6,%7}, {%8,%9}, {%0,%1,%2,%3};"
                 : "+f"(d[0]), "+f"(d[1]), "+f"(d[2]), "+f"(d[3])
                 : "r"(a[0]), "r"(a[1]), "r"(a[2]), "r"(a[3]), "r"(b0), "r"(b1));
}
__device__ __forceinline__ void cpa16(uint32_t s, const void* g) {
    asm volatile("cp.async.cg.shared.global [%0], [%1], 16;" :: "r"(s), "l"(g));
}
__device__ __forceinline__ void cpa_commit() { asm volatile("cp.async.commit_group;"); }

// ---------------- conversion kernels ----------------
__global__ void convert_x_kernel(const float* __restrict__ x,
                                 __nv_bfloat16* __restrict__ xhi,
                                 __nv_bfloat16* __restrict__ xlo, int n4)
{
    int i = blockIdx.x * blockDim.x + threadIdx.x;
    if (i >= n4) return;
    float4 v = reinterpret_cast<const float4*>(x)[i];
    __nv_bfloat16 h0, l0, h1, l1, h2, l2, h3, l3;
    split_bf16(v.x, h0, l0); split_bf16(v.y, h1, l1);
    split_bf16(v.z, h2, l2); split_bf16(v.w, h3, l3);
    reinterpret_cast<__nv_bfloat162*>(xhi)[2 * i]     = __nv_bfloat162(h0, h1);
    reinterpret_cast<__nv_bfloat162*>(xhi)[2 * i + 1] = __nv_bfloat162(h2, h3);
    reinterpret_cast<__nv_bfloat162*>(xlo)[2 * i]     = __nv_bfloat162(l0, l1);
    reinterpret_cast<__nv_bfloat162*>(xlo)[2 * i + 1] = __nv_bfloat162(l2, l3);
}

// Build W' = [Whi | Whi | Wlo] (k' = 3K) for W_fc and both W2 layers.
__global__ void convert_w_kernel(const float* __restrict__ Wfc,
                                 const float* __restrict__ W2,
                                 __nv_bfloat16* __restrict__ Wfc3,
                                 __nv_bfloat16* __restrict__ W23)
{
    int i = blockIdx.x * blockDim.x + threadIdx.x;
    const int t1 = HID * INF;              // W_fc elements
    const int t2 = 2 * HID * HID;          // W2 elements
    if (i < t1) {
        int n = i / INF, k = i % INF;
        __nv_bfloat16 hi, lo; split_bf16(Wfc[i], hi, lo);
        __nv_bfloat16* base = Wfc3 + (size_t)n * (3 * INF);
        base[k] = hi; base[INF + k] = hi; base[2 * INF + k] = lo;
    } else if (i < t1 + t2) {
        int j = i - t1;
        int l = j / (HID * HID); int r = j % (HID * HID);
        int n = r / HID, k = r % HID;
        __nv_bfloat16 hi, lo; split_bf16(W2[j], hi, lo);
        __nv_bfloat16* base = W23 + (size_t)l * HID * (3 * HID) + (size_t)n * (3 * HID);
        base[k] = hi; base[HID + k] = hi; base[2 * HID + k] = lo;
    }
}

// ---------------- tensor-core GEMM -------------------------------------------
// C[M,256] = act(A @ W^T + bias), A given as bf16 hi/lo planes [M,K],
// W' pre-built as [256, 3K] = [Whi|Whi|Wlo]; inner product over k'=3K computes
// AhiWhi + AloWhi + AhiWlo  (segments: A reads hi, lo, hi).
// Block tile 128x64, 8 warps (32x32 each), k-chunk 32, cp.async double buffer.
// OUT=0: write split bf16 planes Chi/Clo.  OUT=1: sigmoid, write fp32 Cf.
#define A_STRIDE 40
#define A_TILE (128 * A_STRIDE)
#define W_TILE (64 * A_STRIDE)

template <int OUT>
__global__ __launch_bounds__(256, 2)
void gemm_tc(const __nv_bfloat16* __restrict__ Ahi, const __nv_bfloat16* __restrict__ Alo,
             const __nv_bfloat16* __restrict__ W3, const float* __restrict__ bias,
             float* __restrict__ Cf, __nv_bfloat16* __restrict__ Chi,
             __nv_bfloat16* __restrict__ Clo, int K)
{
    __shared__ __nv_bfloat16 As[2][A_TILE];
    __shared__ __nv_bfloat16 Ws[2][W_TILE];

    const int tid  = threadIdx.x;
    const int bm   = blockIdx.x * 128;
    const int bn   = blockIdx.y * 64;
    const int warp = tid >> 5;
    const int lane = tid & 31;
    const int K3   = 3 * K;
    const int n1   = K >> 5;            // chunks per segment
    const int nc   = 3 * n1;

    const uint32_t sA = (uint32_t)__cvta_generic_to_shared(&As[0][0]);
    const uint32_t sW = (uint32_t)__cvta_generic_to_shared(&Ws[0][0]);

    // loader mapping (16B units)
    const int ar0 = tid >> 2, ar1 = (tid + 256) >> 2;   // A rows for unit0/1
    const int ac  = (tid & 3) * 8;                       // half offset in chunk
    const int wr  = tid >> 2;                            // W row
    const uint32_t sAoff0 = (uint32_t)(ar0 * A_STRIDE + ac) * 2;
    const uint32_t sAoff1 = (uint32_t)(ar1 * A_STRIDE + ac) * 2;
    const uint32_t sWoff  = (uint32_t)(wr  * A_STRIDE + ac) * 2;
    const __nv_bfloat16* Wg = W3 + (size_t)(bn + wr) * K3 + ac;

    float acc[2][4][4];
#pragma unroll
    for (int a = 0; a < 2; a++)
#pragma unroll
        for (int b = 0; b < 4; b++)
#pragma unroll
            for (int c = 0; c < 4; c++) acc[a][b][c] = 0.0f;

    auto prefetch = [&](int c, int buf) {
        const __nv_bfloat16* Aseg; int kk;
        if (c < n1)           { Aseg = Ahi; kk = c; }
        else if (c < 2 * n1)  { Aseg = Alo; kk = c - n1; }
        else                  { Aseg = Ahi; kk = c - 2 * n1; }
        const __nv_bfloat16* Abase = Aseg + (size_t)bm * K + kk * 32 + ac;
        cpa16(sA + buf * (A_TILE * 2) + sAoff0, Abase + (size_t)ar0 * K);
        cpa16(sA + buf * (A_TILE * 2) + sAoff1, Abase + (size_t)ar1 * K);
        cpa16(sW + buf * (W_TILE * 2) + sWoff,  Wg + c * 32);
    };

    prefetch(0, 0);
    cpa_commit();

    const int wm = warp & 3;   // M band (32 rows)
    const int wn = warp >> 2;  // N band (32 cols)
    // ldmatrix lane addressing (half offsets)
    const int aRow = wm * 32 + (lane & 15);
    const int aColB = (lane >> 4) * 8;
    const int bRow = wn * 32 + (lane & 7) + ((lane >> 4) & 1) * 8;
    const int bColB = ((lane >> 3) & 1) * 8;

    for (int c = 0; c < nc; c++) {
        const int buf = c & 1;
        if (c + 1 < nc) {
            prefetch(c + 1, buf ^ 1);
            cpa_commit();
            asm volatile("cp.async.wait_group 1;");
        } else {
            asm volatile("cp.async.wait_group 0;");
        }
        __syncthreads();

        const uint32_t aBase = sA + buf * (A_TILE * 2);
        const uint32_t wBase = sW + buf * (W_TILE * 2);
#pragma unroll
        for (int ks = 0; ks < 2; ks++) {
            uint32_t afr[2][4], bfr[2][4];
#pragma unroll
            for (int mi = 0; mi < 2; mi++)
                ldsm4(afr[mi], aBase + (uint32_t)((aRow + mi * 16) * A_STRIDE
                                                  + ks * 16 + aColB) * 2);
#pragma unroll
            for (int bi = 0; bi < 2; bi++)
                ldsm4(bfr[bi], wBase + (uint32_t)((bRow + bi * 16) * A_STRIDE
                                                  + ks * 16 + bColB) * 2);
#pragma unroll
            for (int mi = 0; mi < 2; mi++) {
                mma16816(acc[mi][0], afr[mi], bfr[0][0], bfr[0][1]);
                mma16816(acc[mi][1], afr[mi], bfr[0][2], bfr[0][3]);
                mma16816(acc[mi][2], afr[mi], bfr[1][0], bfr[1][1]);
                mma16816(acc[mi][3], afr[mi], bfr[1][2], bfr[1][3]);
            }
        }
        __syncthreads();
    }

    // epilogue
#pragma unroll
    for (int mi = 0; mi < 2; mi++) {
#pragma unroll
        for (int ni = 0; ni < 4; ni++) {
            const int m0 = bm + wm * 32 + mi * 16 + (lane >> 2);
            const int n0 = bn + wn * 32 + ni * 8 + (lane & 3) * 2;
            const float b0 = bias[n0], b1 = bias[n0 + 1];
            float v00 = acc[mi][ni][0] + b0, v01 = acc[mi][ni][1] + b1;
            float v10 = acc[mi][ni][2] + b0, v11 = acc[mi][ni][3] + b1;
            if (OUT == 1) {
                v00 = fast_sigmoid(v00); v01 = fast_sigmoid(v01);
                v10 = fast_sigmoid(v10); v11 = fast_sigmoid(v11);
                *reinterpret_cast<float2*>(Cf + (size_t)m0 * HID + n0)       = make_float2(v00, v01);
                *reinterpret_cast<float2*>(Cf + (size_t)(m0 + 8) * HID + n0) = make_float2(v10, v11);
            } else {
                __nv_bfloat16 h0, l0, h1, l1;
                split_bf16(v00, h0, l0); split_bf16(v01, h1, l1);
                *reinterpret_cast<__nv_bfloat162*>(Chi + (size_t)m0 * HID + n0) = __nv_bfloat162(h0, h1);
                *reinterpret_cast<__nv_bfloat162*>(Clo + (size_t)m0 * HID + n0) = __nv_bfloat162(l0, l1);
                split_bf16(v10, h0, l0); split_bf16(v11, h1, l1);
                *reinterpret_cast<__nv_bfloat162*>(Chi + (size_t)(m0 + 8) * HID + n0) = __nv_bfloat162(h0, h1);
                *reinterpret_cast<__nv_bfloat162*>(Clo + (size_t)(m0 + 8) * HID + n0) = __nv_bfloat162(l0, l1);
            }
        }
    }
}

// ---------------- sequential scan (both directions in one launch) ------------
// h' = tanh(x * (g*h + (1-g)*x)); tanh via ex2/rcp (MUFU): chain ~48 cyc/step.
// OM=0: write split bf16 planes. OM=1: write fp32 strided into d_out.
#define SU 8
template <int OM>
__global__ __launch_bounds__(64)
void scan_tc(const __nv_bfloat16* __restrict__ xAhi, const __nv_bfloat16* __restrict__ xAlo,
             const float* __restrict__ gA,
             const __nv_bfloat16* __restrict__ xBhi, const __nv_bfloat16* __restrict__ xBlo,
             const float* __restrict__ gB,
             __nv_bfloat16* __restrict__ yAhi, __nv_bfloat16* __restrict__ yAlo,
             __nv_bfloat16* __restrict__ yBhi, __nv_bfloat16* __restrict__ yBlo,
             float* __restrict__ outF, int yoffA, int yoffB,
             float* __restrict__ hA, float* __restrict__ hB)
{
    const int gid = blockIdx.x * 64 + threadIdx.x;   // 0..16383
    const int dir = gid >> 13;
    const int id  = gid & 8191;
    const int b = id >> 8;
    const int j = id & 255;

    const __nv_bfloat16 *xh, *xl;
    const float* gp;
    __nv_bfloat16 *yh, *yl;
    float* hp;
    int t0, dt, yo;
    if (dir == 0) { xh = xAhi; xl = xAlo; gp = gA; yh = yAhi; yl = yAlo;
                    hp = hA; t0 = 0;        dt =  1; yo = yoffA; }
    else          { xh = xBhi; xl = xBlo; gp = gB; yh = yBhi; yl = yBlo;
                    hp = hB; t0 = SEQL - 1; dt = -1; yo = yoffB; }

    const int base  = b * SEQL * HID + j;
    const size_t ybase = (size_t)b * SEQL * (2 * HID) + yo + j;

    float xk_a[SU], gx_a[SU], gg_a[SU];
    float xk_b[SU], gx_b[SU], gg_b[SU];

    auto LOAD = [&](int s0, float* xk, float* gx, float* gg) {
#pragma unroll
        for (int u = 0; u < SU; u++) {
            const int t = t0 + dt * (s0 + u);
            const int idx = base + t * HID;
            const float xv = __bfloat162float(xh[idx]) + __bfloat162float(xl[idx]);
            const float g  = __ldg(gp + idx);
            gg[u] = g;
            gx[u] = (1.0f - g) * xv;
            xk[u] = xv * 2.8853900817779268f;   // 2*log2(e)
        }
    };

    LOAD(0, xk_a, gx_a, gg_a);
    float h = 0.0f;
    for (int s0 = 0; s0 < SEQL; s0 += SU) {
        const bool more = (s0 + SU) < SEQL;
        if (more) LOAD(s0 + SU, xk_b, gx_b, gg_b);
#pragma unroll
        for (int u = 0; u < SU; u++) {
            const float r = fmaf(gg_a[u], h, gx_a[u]);
            const float t = fast_ex2(xk_a[u] * r);
            h = fmaf(-2.0f, fast_rcp(t + 1.0f), 1.0f);
            const int tt = t0 + dt * (s0 + u);
            if (OM == 0) {
                __nv_bfloat16 hi, lo; split_bf16(h, hi, lo);
                yh[base + tt * HID] = hi;
                yl[base + tt * HID] = lo;
            } else {
                outF[ybase + (size_t)tt * (2 * HID)] = h;
            }
        }
        if (more) {
#pragma unroll
            for (int u = 0; u < SU; u++) {
                xk_a[u] = xk_b[u]; gx_a[u] = gx_b[u]; gg_a[u] = gg_b[u];
            }
        }
    }
    hp[(b << 8) + j] = h;
}

// ---------------- launch ----------------
extern "C" void kernel_launch(void* const* d_in, const int* in_sizes, int n_in,
                              void* d_out, int out_size)
{
    const float* x    = (const float*)d_in[0];  // [32,2048,512]
    const float* W_fc = (const float*)d_in[1];  // [256,512]
    const float* b_fc = (const float*)d_in[2];  // [256]
    // d_in[3] (W1), d_in[4] (b1): mathematically dead (blending1 == identity)
    const float* W2   = (const float*)d_in[5];  // [2,256,256]
    const float* b2   = (const float*)d_in[6];  // [2,256]
    float* out = (float*)d_out;

    __nv_bfloat16 *xhi, *xlo, *Wfc3, *W23, *Hhi, *Hlo, *Ylhi, *Yllo, *Yrhi, *Yrlo;
    float *G1, *Ga, *Gb, *hd;
    cudaGetSymbolAddress((void**)&xhi,  g_xhi);
    cudaGetSymbolAddress((void**)&xlo,  g_xlo);
    cudaGetSymbolAddress((void**)&Wfc3, g_Wfc3);
    cudaGetSymbolAddress((void**)&W23,  g_W23);
    cudaGetSymbolAddress((void**)&Hhi,  g_Hhi);
    cudaGetSymbolAddress((void**)&Hlo,  g_Hlo);
    cudaGetSymbolAddress((void**)&G1,   g_G1);
    cudaGetSymbolAddress((void**)&Ylhi, g_Ylhi);
    cudaGetSymbolAddress((void**)&Yllo, g_Yllo);
    cudaGetSymbolAddress((void**)&Yrhi, g_Yrhi);
    cudaGetSymbolAddress((void**)&Yrlo, g_Yrlo);
    cudaGetSymbolAddress((void**)&Ga,   g_Ga);
    cudaGetSymbolAddress((void**)&Gb,   g_Gb);
    cudaGetSymbolAddress((void**)&hd,   g_hdump);

    float* hout = (out_size >= XXN + HOUTN) ? (out + XXN) : hd;

    // 0) operand conversion (x -> hi/lo planes; W -> [Whi|Whi|Wlo])
    {
        int n4 = MTOT * INF / 4;
        convert_x_kernel<<<(n4 + 255) / 256, 256>>>(x, xhi, xlo, n4);
        int nw = HID * INF + 2 * HID * HID;
        convert_w_kernel<<<(nw + 255) / 256, 256>>>(W_fc, W2, Wfc3, W23);
    }

    const dim3 blk(256);
    const dim3 grd(MTOT / 128, HID / 64);

    // 1) input projection -> split bf16 H planes
    gemm_tc<0><<<grd, blk>>>(xhi, xlo, Wfc3, b_fc, nullptr, Hhi, Hlo, INF);
    // 2) layer-1 gates (shared by both directions)
    gemm_tc<1><<<grd, blk>>>(Hhi, Hlo, W23, b2, G1, nullptr, nullptr, HID);
    // 3) layer-1 scans -> split Y planes (+ h_out rows 0,1)
    scan_tc<0><<<256, 64>>>(Hhi, Hlo, G1, Hhi, Hlo, G1,
                            Ylhi, Yllo, Yrhi, Yrlo,
                            nullptr, 0, 0, hout, hout + BSZ * HID);
    // 4) layer-2 gates (per direction)
    gemm_tc<1><<<grd, blk>>>(Ylhi, Yllo, W23 + (size_t)HID * 3 * HID, b2 + HID,
                             Ga, nullptr, nullptr, HID);
    gemm_tc<1><<<grd, blk>>>(Yrhi, Yrlo, W23 + (size_t)HID * 3 * HID, b2 + HID,
                             Gb, nullptr, nullptr, HID);
    // 5) layer-2 scans write straight into d_out xx[:,:,0:256] / [:,:,256:512]
    scan_tc<1><<<256, 64>>>(Ylhi, Yllo, Ga, Yrhi, Yrlo, Gb,
                            nullptr, nullptr, nullptr, nullptr,
                            out, 0, HID, hout + 2 * BSZ * HID, hout + 3 * BSZ * HID);
}